// round 1
// baseline (speedup 1.0000x reference)
#include <cuda_runtime.h>
#include <math.h>

#define N_TOK   4096
#define DIM     1024
#define HEADS   8
#define DHEAD   64
#define DINNER  512
#define QKV_N   1536

// Scratch (allocation-free rule: __device__ globals)
__device__ float g_scale[N_TOK];
__device__ float g_qkv[(size_t)N_TOK * QKV_N];
__device__ float g_ao[(size_t)N_TOK * DINNER];

// ---------------------------------------------------------------------------
// Kernel 1: per-row RMS scale = sqrt(DIM) / max(||x_row||, 1e-12)
// ---------------------------------------------------------------------------
__global__ void rms_scale_kernel(const float* __restrict__ x) {
    int row = blockIdx.x;
    const float* xr = x + (size_t)row * DIM;
    float s = 0.f;
    for (int i = threadIdx.x; i < DIM; i += 256) {
        float v = xr[i];
        s += v * v;
    }
    #pragma unroll
    for (int o = 16; o; o >>= 1) s += __shfl_xor_sync(0xffffffffu, s, o);
    __shared__ float ws[8];
    if ((threadIdx.x & 31) == 0) ws[threadIdx.x >> 5] = s;
    __syncthreads();
    if (threadIdx.x == 0) {
        float t = 0.f;
        #pragma unroll
        for (int i = 0; i < 8; i++) t += ws[i];
        float norm = sqrtf(t);
        g_scale[row] = 32.0f / fmaxf(norm, 1e-12f);  // sqrt(1024) = 32
    }
}

// ---------------------------------------------------------------------------
// Tiled fp32 GEMM: C[M,N] = A[M,K] @ B[K,N], BM=BN=64, BK=16, 256 threads,
// 4x4 micro-tile per thread. Optionally fuses rmsnorm scale (per A-row) and
// gamma (per A-column) into the A tile load.
// ---------------------------------------------------------------------------
template <bool FUSE_RMS>
__global__ __launch_bounds__(256)
void gemm64_kernel(const float* __restrict__ A, const float* __restrict__ B,
                   float* __restrict__ C, int M, int N, int K,
                   const float* __restrict__ rowscale,
                   const float* __restrict__ gamma) {
    __shared__ float As[16][68];
    __shared__ float Bs[16][68];
    int tid = threadIdx.x;
    int tx = tid & 15, ty = tid >> 4;
    int m0 = blockIdx.y * 64, n0 = blockIdx.x * 64;

    int lrow = tid >> 2;          // 0..63  (A loader row)
    int lk   = (tid & 3) * 4;     // 0,4,8,12
    int brow = tid >> 4;          // 0..15  (B loader k-row)
    int bcol = (tid & 15) * 4;

    float rs = FUSE_RMS ? rowscale[m0 + lrow] : 0.f;

    float acc[4][4];
    #pragma unroll
    for (int i = 0; i < 4; i++)
        #pragma unroll
        for (int j = 0; j < 4; j++) acc[i][j] = 0.f;

    for (int k0 = 0; k0 < K; k0 += 16) {
        float4 a4 = *(const float4*)(A + (size_t)(m0 + lrow) * K + k0 + lk);
        if (FUSE_RMS) {
            a4.x *= rs * gamma[k0 + lk + 0];
            a4.y *= rs * gamma[k0 + lk + 1];
            a4.z *= rs * gamma[k0 + lk + 2];
            a4.w *= rs * gamma[k0 + lk + 3];
        }
        As[lk + 0][lrow] = a4.x;
        As[lk + 1][lrow] = a4.y;
        As[lk + 2][lrow] = a4.z;
        As[lk + 3][lrow] = a4.w;
        *(float4*)&Bs[brow][bcol] =
            *(const float4*)(B + (size_t)(k0 + brow) * N + n0 + bcol);
        __syncthreads();
        #pragma unroll
        for (int kk = 0; kk < 16; kk++) {
            float4 a = *(const float4*)&As[kk][ty * 4];
            float4 b = *(const float4*)&Bs[kk][tx * 4];
            float av[4] = {a.x, a.y, a.z, a.w};
            float bv[4] = {b.x, b.y, b.z, b.w};
            #pragma unroll
            for (int i = 0; i < 4; i++)
                #pragma unroll
                for (int j = 0; j < 4; j++)
                    acc[i][j] += av[i] * bv[j];
        }
        __syncthreads();
    }
    #pragma unroll
    for (int i = 0; i < 4; i++) {
        float4 r = make_float4(acc[i][0], acc[i][1], acc[i][2], acc[i][3]);
        *(float4*)(C + (size_t)(m0 + ty * 4 + i) * N + n0 + tx * 4) = r;
    }
}

// ---------------------------------------------------------------------------
// Kernel 3: causal flash attention.
// Grid (64 qtiles, 8 heads), 256 threads. Each thread owns one query row
// (r = tid>>2) jointly with its quad (q = tid&3): quad splits the 64 key
// columns (j = 4*jj + q, conflict-free smem pattern) and the 64 output dims
// (d = q*4 + c*16). Online softmax with quad shfl reductions.
// q is pre-scaled by sqrt(d)=8 as in the reference.
// ---------------------------------------------------------------------------
__global__ __launch_bounds__(256)
void attn_kernel(const float* __restrict__ qkv, float* __restrict__ ao) {
    int qt = gridDim.x - 1 - blockIdx.x;   // heavy (late) tiles first
    int h  = blockIdx.y;
    __shared__ float Ks[64][68];
    __shared__ float Vs[64][68];

    int tid = threadIdx.x;
    int r = tid >> 2;
    int q = tid & 3;
    int grow = qt * 64 + r;

    float qreg[64];
    {
        const float* qp = qkv + (size_t)grow * QKV_N + h * DHEAD;
        #pragma unroll
        for (int d4 = 0; d4 < 16; d4++) {
            float4 v = *(const float4*)(qp + d4 * 4);
            qreg[d4 * 4 + 0] = v.x * 8.f;
            qreg[d4 * 4 + 1] = v.y * 8.f;
            qreg[d4 * 4 + 2] = v.z * 8.f;
            qreg[d4 * 4 + 3] = v.w * 8.f;
        }
    }

    float o[16];
    #pragma unroll
    for (int i = 0; i < 16; i++) o[i] = 0.f;
    float mrow = -1e30f, lrow = 0.f;

    for (int kt = 0; kt <= qt; kt++) {
        __syncthreads();   // protect previous iteration's Ks/Vs reads
        for (int e = tid; e < 4096; e += 256) {
            int rr = e >> 6, d = e & 63;
            const float* base =
                qkv + (size_t)(kt * 64 + rr) * QKV_N + h * DHEAD + d;
            Ks[rr][d] = base[DINNER];
            Vs[rr][d] = base[2 * DINNER];
        }
        __syncthreads();

        // S = Q K^T for this thread's 16 columns (j = 4*jj + q)
        float s[16];
        #pragma unroll
        for (int jj = 0; jj < 16; jj++) {
            int j = 4 * jj + q;
            float acc = 0.f;
            #pragma unroll
            for (int d4 = 0; d4 < 16; d4++) {
                float4 kv = *(const float4*)&Ks[j][d4 * 4];
                acc += qreg[d4 * 4 + 0] * kv.x;
                acc += qreg[d4 * 4 + 1] * kv.y;
                acc += qreg[d4 * 4 + 2] * kv.z;
                acc += qreg[d4 * 4 + 3] * kv.w;
            }
            int gj = kt * 64 + j;
            s[jj] = (gj <= grow) ? acc : -1e30f;
        }

        // online softmax: row max over quad
        float tmax = s[0];
        #pragma unroll
        for (int jj = 1; jj < 16; jj++) tmax = fmaxf(tmax, s[jj]);
        tmax = fmaxf(tmax, __shfl_xor_sync(0xffffffffu, tmax, 1, 4));
        tmax = fmaxf(tmax, __shfl_xor_sync(0xffffffffu, tmax, 2, 4));
        float mnew = fmaxf(mrow, tmax);
        float corr = __expf(mrow - mnew);
        lrow *= corr;
        #pragma unroll
        for (int i = 0; i < 16; i++) o[i] *= corr;

        float psum = 0.f;
        #pragma unroll
        for (int jj = 0; jj < 16; jj++) {
            s[jj] = __expf(s[jj] - mnew);
            psum += s[jj];
        }
        psum += __shfl_xor_sync(0xffffffffu, psum, 1, 4);
        psum += __shfl_xor_sync(0xffffffffu, psum, 2, 4);
        lrow += psum;
        mrow = mnew;

        // o += P @ V  (broadcast P across quad via shfl; thread owns dims
        // d = q*4 + c*16 + i  → conflict-free Vs float4 reads)
        #pragma unroll
        for (int jj = 0; jj < 16; jj++) {
            #pragma unroll
            for (int sq = 0; sq < 4; sq++) {
                float p = __shfl_sync(0xffffffffu, s[jj], sq, 4);
                int j = 4 * jj + sq;
                #pragma unroll
                for (int c = 0; c < 4; c++) {
                    float4 v = *(const float4*)&Vs[j][q * 4 + c * 16];
                    o[c * 4 + 0] += p * v.x;
                    o[c * 4 + 1] += p * v.y;
                    o[c * 4 + 2] += p * v.z;
                    o[c * 4 + 3] += p * v.w;
                }
            }
        }
    }

    float inv = 1.f / lrow;
    float* op = ao + (size_t)grow * DINNER + h * DHEAD;
    #pragma unroll
    for (int c = 0; c < 4; c++) {
        float4 v = make_float4(o[c * 4 + 0] * inv, o[c * 4 + 1] * inv,
                               o[c * 4 + 2] * inv, o[c * 4 + 3] * inv);
        *(float4*)(op + q * 4 + c * 16) = v;
    }
}

// ---------------------------------------------------------------------------
extern "C" void kernel_launch(void* const* d_in, const int* in_sizes, int n_in,
                              void* d_out, int out_size) {
    const float* x     = (const float*)d_in[0];
    const float* gamma = (const float*)d_in[1];
    const float* w_qkv = (const float*)d_in[2];
    const float* w_out = (const float*)d_in[3];
    float* out = (float*)d_out;

    float *scale_p, *qkv_p, *ao_p;
    cudaGetSymbolAddress((void**)&scale_p, g_scale);
    cudaGetSymbolAddress((void**)&qkv_p, g_qkv);
    cudaGetSymbolAddress((void**)&ao_p, g_ao);

    rms_scale_kernel<<<N_TOK, 256>>>(x);

    gemm64_kernel<true><<<dim3(QKV_N / 64, N_TOK / 64), 256>>>(
        x, w_qkv, qkv_p, N_TOK, QKV_N, DIM, scale_p, gamma);

    attn_kernel<<<dim3(64, 8), 256>>>(qkv_p, ao_p);

    gemm64_kernel<false><<<dim3(DIM / 64, N_TOK / 64), 256>>>(
        ao_p, w_out, out, N_TOK, DIM, DINNER, nullptr, nullptr);
}

// round 2
// speedup vs baseline: 1.0003x; 1.0003x over previous
#include <cuda_runtime.h>
#include <math.h>

#define N_TOK   4096
#define DIM     1024
#define HEADS   8
#define DHEAD   64
#define DINNER  512
#define QKV_N   1536

// Scratch (allocation-free rule: __device__ globals)
__device__ float g_scale[N_TOK];
__device__ float g_qkv[(size_t)N_TOK * QKV_N];
__device__ float g_ao[(size_t)N_TOK * DINNER];

// ---------------------------------------------------------------------------
// Kernel 1: per-row RMS scale = sqrt(DIM) / max(||x_row||, 1e-12)
// ---------------------------------------------------------------------------
__global__ void rms_scale_kernel(const float* __restrict__ x) {
    int row = blockIdx.x;
    const float* xr = x + (size_t)row * DIM;
    float s = 0.f;
    for (int i = threadIdx.x; i < DIM; i += 256) {
        float v = xr[i];
        s += v * v;
    }
    #pragma unroll
    for (int o = 16; o; o >>= 1) s += __shfl_xor_sync(0xffffffffu, s, o);
    __shared__ float ws[8];
    if ((threadIdx.x & 31) == 0) ws[threadIdx.x >> 5] = s;
    __syncthreads();
    if (threadIdx.x == 0) {
        float t = 0.f;
        #pragma unroll
        for (int i = 0; i < 8; i++) t += ws[i];
        float norm = sqrtf(t);
        g_scale[row] = 32.0f / fmaxf(norm, 1e-12f);  // sqrt(1024) = 32
    }
}

// ---------------------------------------------------------------------------
// Tiled fp32 GEMM: C[M,N] = A[M,K] @ B[K,N], BM=BN=64, BK=16, 256 threads,
// 4x4 micro-tile per thread. Optionally fuses rmsnorm scale (per A-row) and
// gamma (per A-column) into the A tile load.
// ---------------------------------------------------------------------------
template <bool FUSE_RMS>
__global__ __launch_bounds__(256)
void gemm64_kernel(const float* __restrict__ A, const float* __restrict__ B,
                   float* __restrict__ C, int M, int N, int K,
                   const float* __restrict__ rowscale,
                   const float* __restrict__ gamma) {
    __shared__ float As[16][68];
    __shared__ float Bs[16][68];
    int tid = threadIdx.x;
    int tx = tid & 15, ty = tid >> 4;
    int m0 = blockIdx.y * 64, n0 = blockIdx.x * 64;

    int lrow = tid >> 2;          // 0..63  (A loader row)
    int lk   = (tid & 3) * 4;     // 0,4,8,12
    int brow = tid >> 4;          // 0..15  (B loader k-row)
    int bcol = (tid & 15) * 4;

    float rs = FUSE_RMS ? rowscale[m0 + lrow] : 0.f;

    float acc[4][4];
    #pragma unroll
    for (int i = 0; i < 4; i++)
        #pragma unroll
        for (int j = 0; j < 4; j++) acc[i][j] = 0.f;

    for (int k0 = 0; k0 < K; k0 += 16) {
        float4 a4 = *(const float4*)(A + (size_t)(m0 + lrow) * K + k0 + lk);
        if (FUSE_RMS) {
            a4.x *= rs * gamma[k0 + lk + 0];
            a4.y *= rs * gamma[k0 + lk + 1];
            a4.z *= rs * gamma[k0 + lk + 2];
            a4.w *= rs * gamma[k0 + lk + 3];
        }
        As[lk + 0][lrow] = a4.x;
        As[lk + 1][lrow] = a4.y;
        As[lk + 2][lrow] = a4.z;
        As[lk + 3][lrow] = a4.w;
        *(float4*)&Bs[brow][bcol] =
            *(const float4*)(B + (size_t)(k0 + brow) * N + n0 + bcol);
        __syncthreads();
        #pragma unroll
        for (int kk = 0; kk < 16; kk++) {
            float4 a = *(const float4*)&As[kk][ty * 4];
            float4 b = *(const float4*)&Bs[kk][tx * 4];
            float av[4] = {a.x, a.y, a.z, a.w};
            float bv[4] = {b.x, b.y, b.z, b.w};
            #pragma unroll
            for (int i = 0; i < 4; i++)
                #pragma unroll
                for (int j = 0; j < 4; j++)
                    acc[i][j] += av[i] * bv[j];
        }
        __syncthreads();
    }
    #pragma unroll
    for (int i = 0; i < 4; i++) {
        float4 r = make_float4(acc[i][0], acc[i][1], acc[i][2], acc[i][3]);
        *(float4*)(C + (size_t)(m0 + ty * 4 + i) * N + n0 + tx * 4) = r;
    }
}

// ---------------------------------------------------------------------------
// Kernel 3: causal flash attention.
// Grid (64 qtiles, 8 heads), 256 threads. Each thread owns one query row
// (r = tid>>2) jointly with its quad (q = tid&3): quad splits the 64 key
// columns (j = 4*jj + q, conflict-free smem pattern) and the 64 output dims
// (d = q*4 + c*16). Online softmax with quad shfl reductions.
// q is pre-scaled by sqrt(d)=8 as in the reference.
// ---------------------------------------------------------------------------
__global__ __launch_bounds__(256)
void attn_kernel(const float* __restrict__ qkv, float* __restrict__ ao) {
    int qt = gridDim.x - 1 - blockIdx.x;   // heavy (late) tiles first
    int h  = blockIdx.y;
    __shared__ float Ks[64][68];
    __shared__ float Vs[64][68];

    int tid = threadIdx.x;
    int r = tid >> 2;
    int q = tid & 3;
    int grow = qt * 64 + r;

    float qreg[64];
    {
        const float* qp = qkv + (size_t)grow * QKV_N + h * DHEAD;
        #pragma unroll
        for (int d4 = 0; d4 < 16; d4++) {
            float4 v = *(const float4*)(qp + d4 * 4);
            qreg[d4 * 4 + 0] = v.x * 8.f;
            qreg[d4 * 4 + 1] = v.y * 8.f;
            qreg[d4 * 4 + 2] = v.z * 8.f;
            qreg[d4 * 4 + 3] = v.w * 8.f;
        }
    }

    float o[16];
    #pragma unroll
    for (int i = 0; i < 16; i++) o[i] = 0.f;
    float mrow = -1e30f, lrow = 0.f;

    for (int kt = 0; kt <= qt; kt++) {
        __syncthreads();   // protect previous iteration's Ks/Vs reads
        for (int e = tid; e < 4096; e += 256) {
            int rr = e >> 6, d = e & 63;
            const float* base =
                qkv + (size_t)(kt * 64 + rr) * QKV_N + h * DHEAD + d;
            Ks[rr][d] = base[DINNER];
            Vs[rr][d] = base[2 * DINNER];
        }
        __syncthreads();

        // S = Q K^T for this thread's 16 columns (j = 4*jj + q)
        float s[16];
        #pragma unroll
        for (int jj = 0; jj < 16; jj++) {
            int j = 4 * jj + q;
            float acc = 0.f;
            #pragma unroll
            for (int d4 = 0; d4 < 16; d4++) {
                float4 kv = *(const float4*)&Ks[j][d4 * 4];
                acc += qreg[d4 * 4 + 0] * kv.x;
                acc += qreg[d4 * 4 + 1] * kv.y;
                acc += qreg[d4 * 4 + 2] * kv.z;
                acc += qreg[d4 * 4 + 3] * kv.w;
            }
            int gj = kt * 64 + j;
            s[jj] = (gj <= grow) ? acc : -1e30f;
        }

        // online softmax: row max over quad
        float tmax = s[0];
        #pragma unroll
        for (int jj = 1; jj < 16; jj++) tmax = fmaxf(tmax, s[jj]);
        tmax = fmaxf(tmax, __shfl_xor_sync(0xffffffffu, tmax, 1, 4));
        tmax = fmaxf(tmax, __shfl_xor_sync(0xffffffffu, tmax, 2, 4));
        float mnew = fmaxf(mrow, tmax);
        float corr = __expf(mrow - mnew);
        lrow *= corr;
        #pragma unroll
        for (int i = 0; i < 16; i++) o[i] *= corr;

        float psum = 0.f;
        #pragma unroll
        for (int jj = 0; jj < 16; jj++) {
            s[jj] = __expf(s[jj] - mnew);
            psum += s[jj];
        }
        psum += __shfl_xor_sync(0xffffffffu, psum, 1, 4);
        psum += __shfl_xor_sync(0xffffffffu, psum, 2, 4);
        lrow += psum;
        mrow = mnew;

        // o += P @ V  (broadcast P across quad via shfl; thread owns dims
        // d = q*4 + c*16 + i  → conflict-free Vs float4 reads)
        #pragma unroll
        for (int jj = 0; jj < 16; jj++) {
            #pragma unroll
            for (int sq = 0; sq < 4; sq++) {
                float p = __shfl_sync(0xffffffffu, s[jj], sq, 4);
                int j = 4 * jj + sq;
                #pragma unroll
                for (int c = 0; c < 4; c++) {
                    float4 v = *(const float4*)&Vs[j][q * 4 + c * 16];
                    o[c * 4 + 0] += p * v.x;
                    o[c * 4 + 1] += p * v.y;
                    o[c * 4 + 2] += p * v.z;
                    o[c * 4 + 3] += p * v.w;
                }
            }
        }
    }

    float inv = 1.f / lrow;
    float* op = ao + (size_t)grow * DINNER + h * DHEAD;
    #pragma unroll
    for (int c = 0; c < 4; c++) {
        float4 v = make_float4(o[c * 4 + 0] * inv, o[c * 4 + 1] * inv,
                               o[c * 4 + 2] * inv, o[c * 4 + 3] * inv);
        *(float4*)(op + q * 4 + c * 16) = v;
    }
}

// ---------------------------------------------------------------------------
extern "C" void kernel_launch(void* const* d_in, const int* in_sizes, int n_in,
                              void* d_out, int out_size) {
    const float* x     = (const float*)d_in[0];
    const float* gamma = (const float*)d_in[1];
    const float* w_qkv = (const float*)d_in[2];
    const float* w_out = (const float*)d_in[3];
    float* out = (float*)d_out;

    float *scale_p, *qkv_p, *ao_p;
    cudaGetSymbolAddress((void**)&scale_p, g_scale);
    cudaGetSymbolAddress((void**)&qkv_p, g_qkv);
    cudaGetSymbolAddress((void**)&ao_p, g_ao);

    rms_scale_kernel<<<N_TOK, 256>>>(x);

    gemm64_kernel<true><<<dim3(QKV_N / 64, N_TOK / 64), 256>>>(
        x, w_qkv, qkv_p, N_TOK, QKV_N, DIM, scale_p, gamma);

    attn_kernel<<<dim3(64, 8), 256>>>(qkv_p, ao_p);

    gemm64_kernel<false><<<dim3(DIM / 64, N_TOK / 64), 256>>>(
        ao_p, w_out, out, N_TOK, DIM, DINNER, nullptr, nullptr);
}

// round 3
// speedup vs baseline: 1.0013x; 1.0010x over previous
#include <cuda_runtime.h>
#include <math.h>

#define N_TOK   4096
#define DIM     1024
#define HEADS   8
#define DHEAD   64
#define DINNER  512
#define QKV_N   1536

// Scratch (allocation-free rule: __device__ globals)
__device__ float g_scale[N_TOK];
__device__ float g_qkv[(size_t)N_TOK * QKV_N];
__device__ float g_ao[(size_t)N_TOK * DINNER];

// ---------------------------------------------------------------------------
// Kernel 1: per-row RMS scale = sqrt(DIM) / max(||x_row||, 1e-12)
// ---------------------------------------------------------------------------
__global__ void rms_scale_kernel(const float* __restrict__ x) {
    int row = blockIdx.x;
    const float* xr = x + (size_t)row * DIM;
    float s = 0.f;
    for (int i = threadIdx.x; i < DIM; i += 256) {
        float v = xr[i];
        s += v * v;
    }
    #pragma unroll
    for (int o = 16; o; o >>= 1) s += __shfl_xor_sync(0xffffffffu, s, o);
    __shared__ float ws[8];
    if ((threadIdx.x & 31) == 0) ws[threadIdx.x >> 5] = s;
    __syncthreads();
    if (threadIdx.x == 0) {
        float t = 0.f;
        #pragma unroll
        for (int i = 0; i < 8; i++) t += ws[i];
        float norm = sqrtf(t);
        g_scale[row] = 32.0f / fmaxf(norm, 1e-12f);  // sqrt(1024) = 32
    }
}

// ---------------------------------------------------------------------------
// Tiled fp32 GEMM: C[M,N] = A[M,K] @ B[K,N], BM=BN=64, BK=16, 256 threads,
// 4x4 micro-tile per thread. Optionally fuses rmsnorm scale (per A-row) and
// gamma (per A-column) into the A tile load.
// ---------------------------------------------------------------------------
template <bool FUSE_RMS>
__global__ __launch_bounds__(256)
void gemm64_kernel(const float* __restrict__ A, const float* __restrict__ B,
                   float* __restrict__ C, int M, int N, int K,
                   const float* __restrict__ rowscale,
                   const float* __restrict__ gamma) {
    __shared__ float As[16][68];
    __shared__ float Bs[16][68];
    int tid = threadIdx.x;
    int tx = tid & 15, ty = tid >> 4;
    int m0 = blockIdx.y * 64, n0 = blockIdx.x * 64;

    int lrow = tid >> 2;          // 0..63  (A loader row)
    int lk   = (tid & 3) * 4;     // 0,4,8,12
    int brow = tid >> 4;          // 0..15  (B loader k-row)
    int bcol = (tid & 15) * 4;

    float rs = FUSE_RMS ? rowscale[m0 + lrow] : 0.f;

    float acc[4][4];
    #pragma unroll
    for (int i = 0; i < 4; i++)
        #pragma unroll
        for (int j = 0; j < 4; j++) acc[i][j] = 0.f;

    for (int k0 = 0; k0 < K; k0 += 16) {
        float4 a4 = *(const float4*)(A + (size_t)(m0 + lrow) * K + k0 + lk);
        if (FUSE_RMS) {
            a4.x *= rs * gamma[k0 + lk + 0];
            a4.y *= rs * gamma[k0 + lk + 1];
            a4.z *= rs * gamma[k0 + lk + 2];
            a4.w *= rs * gamma[k0 + lk + 3];
        }
        As[lk + 0][lrow] = a4.x;
        As[lk + 1][lrow] = a4.y;
        As[lk + 2][lrow] = a4.z;
        As[lk + 3][lrow] = a4.w;
        *(float4*)&Bs[brow][bcol] =
            *(const float4*)(B + (size_t)(k0 + brow) * N + n0 + bcol);
        __syncthreads();
        #pragma unroll
        for (int kk = 0; kk < 16; kk++) {
            float4 a = *(const float4*)&As[kk][ty * 4];
            float4 b = *(const float4*)&Bs[kk][tx * 4];
            float av[4] = {a.x, a.y, a.z, a.w};
            float bv[4] = {b.x, b.y, b.z, b.w};
            #pragma unroll
            for (int i = 0; i < 4; i++)
                #pragma unroll
                for (int j = 0; j < 4; j++)
                    acc[i][j] += av[i] * bv[j];
        }
        __syncthreads();
    }
    #pragma unroll
    for (int i = 0; i < 4; i++) {
        float4 r = make_float4(acc[i][0], acc[i][1], acc[i][2], acc[i][3]);
        *(float4*)(C + (size_t)(m0 + ty * 4 + i) * N + n0 + tx * 4) = r;
    }
}

// ---------------------------------------------------------------------------
// Kernel 3: causal flash attention.
// Grid (64 qtiles, 8 heads), 256 threads. Each thread owns one query row
// (r = tid>>2) jointly with its quad (q = tid&3): quad splits the 64 key
// columns (j = 4*jj + q, conflict-free smem pattern) and the 64 output dims
// (d = q*4 + c*16). Online softmax with quad shfl reductions.
// q is pre-scaled by sqrt(d)=8 as in the reference.
// ---------------------------------------------------------------------------
__global__ __launch_bounds__(256)
void attn_kernel(const float* __restrict__ qkv, float* __restrict__ ao) {
    int qt = gridDim.x - 1 - blockIdx.x;   // heavy (late) tiles first
    int h  = blockIdx.y;
    __shared__ float Ks[64][68];
    __shared__ float Vs[64][68];

    int tid = threadIdx.x;
    int r = tid >> 2;
    int q = tid & 3;
    int grow = qt * 64 + r;

    float qreg[64];
    {
        const float* qp = qkv + (size_t)grow * QKV_N + h * DHEAD;
        #pragma unroll
        for (int d4 = 0; d4 < 16; d4++) {
            float4 v = *(const float4*)(qp + d4 * 4);
            qreg[d4 * 4 + 0] = v.x * 8.f;
            qreg[d4 * 4 + 1] = v.y * 8.f;
            qreg[d4 * 4 + 2] = v.z * 8.f;
            qreg[d4 * 4 + 3] = v.w * 8.f;
        }
    }

    float o[16];
    #pragma unroll
    for (int i = 0; i < 16; i++) o[i] = 0.f;
    float mrow = -1e30f, lrow = 0.f;

    for (int kt = 0; kt <= qt; kt++) {
        __syncthreads();   // protect previous iteration's Ks/Vs reads
        for (int e = tid; e < 4096; e += 256) {
            int rr = e >> 6, d = e & 63;
            const float* base =
                qkv + (size_t)(kt * 64 + rr) * QKV_N + h * DHEAD + d;
            Ks[rr][d] = base[DINNER];
            Vs[rr][d] = base[2 * DINNER];
        }
        __syncthreads();

        // S = Q K^T for this thread's 16 columns (j = 4*jj + q)
        float s[16];
        #pragma unroll
        for (int jj = 0; jj < 16; jj++) {
            int j = 4 * jj + q;
            float acc = 0.f;
            #pragma unroll
            for (int d4 = 0; d4 < 16; d4++) {
                float4 kv = *(const float4*)&Ks[j][d4 * 4];
                acc += qreg[d4 * 4 + 0] * kv.x;
                acc += qreg[d4 * 4 + 1] * kv.y;
                acc += qreg[d4 * 4 + 2] * kv.z;
                acc += qreg[d4 * 4 + 3] * kv.w;
            }
            int gj = kt * 64 + j;
            s[jj] = (gj <= grow) ? acc : -1e30f;
        }

        // online softmax: row max over quad
        float tmax = s[0];
        #pragma unroll
        for (int jj = 1; jj < 16; jj++) tmax = fmaxf(tmax, s[jj]);
        tmax = fmaxf(tmax, __shfl_xor_sync(0xffffffffu, tmax, 1, 4));
        tmax = fmaxf(tmax, __shfl_xor_sync(0xffffffffu, tmax, 2, 4));
        float mnew = fmaxf(mrow, tmax);
        float corr = __expf(mrow - mnew);
        lrow *= corr;
        #pragma unroll
        for (int i = 0; i < 16; i++) o[i] *= corr;

        float psum = 0.f;
        #pragma unroll
        for (int jj = 0; jj < 16; jj++) {
            s[jj] = __expf(s[jj] - mnew);
            psum += s[jj];
        }
        psum += __shfl_xor_sync(0xffffffffu, psum, 1, 4);
        psum += __shfl_xor_sync(0xffffffffu, psum, 2, 4);
        lrow += psum;
        mrow = mnew;

        // o += P @ V  (broadcast P across quad via shfl; thread owns dims
        // d = q*4 + c*16 + i  → conflict-free Vs float4 reads)
        #pragma unroll
        for (int jj = 0; jj < 16; jj++) {
            #pragma unroll
            for (int sq = 0; sq < 4; sq++) {
                float p = __shfl_sync(0xffffffffu, s[jj], sq, 4);
                int j = 4 * jj + sq;
                #pragma unroll
                for (int c = 0; c < 4; c++) {
                    float4 v = *(const float4*)&Vs[j][q * 4 + c * 16];
                    o[c * 4 + 0] += p * v.x;
                    o[c * 4 + 1] += p * v.y;
                    o[c * 4 + 2] += p * v.z;
                    o[c * 4 + 3] += p * v.w;
                }
            }
        }
    }

    float inv = 1.f / lrow;
    float* op = ao + (size_t)grow * DINNER + h * DHEAD;
    #pragma unroll
    for (int c = 0; c < 4; c++) {
        float4 v = make_float4(o[c * 4 + 0] * inv, o[c * 4 + 1] * inv,
                               o[c * 4 + 2] * inv, o[c * 4 + 3] * inv);
        *(float4*)(op + q * 4 + c * 16) = v;
    }
}

// ---------------------------------------------------------------------------
extern "C" void kernel_launch(void* const* d_in, const int* in_sizes, int n_in,
                              void* d_out, int out_size) {
    const float* x     = (const float*)d_in[0];
    const float* gamma = (const float*)d_in[1];
    const float* w_qkv = (const float*)d_in[2];
    const float* w_out = (const float*)d_in[3];
    float* out = (float*)d_out;

    float *scale_p, *qkv_p, *ao_p;
    cudaGetSymbolAddress((void**)&scale_p, g_scale);
    cudaGetSymbolAddress((void**)&qkv_p, g_qkv);
    cudaGetSymbolAddress((void**)&ao_p, g_ao);

    rms_scale_kernel<<<N_TOK, 256>>>(x);

    gemm64_kernel<true><<<dim3(QKV_N / 64, N_TOK / 64), 256>>>(
        x, w_qkv, qkv_p, N_TOK, QKV_N, DIM, scale_p, gamma);

    attn_kernel<<<dim3(64, 8), 256>>>(qkv_p, ao_p);

    gemm64_kernel<false><<<dim3(DIM / 64, N_TOK / 64), 256>>>(
        ao_p, w_out, out, N_TOK, DIM, DINNER, nullptr, nullptr);
}

// round 4
// speedup vs baseline: 1.2578x; 1.2561x over previous
#include <cuda_runtime.h>
#include <math.h>

#define N_TOK   4096
#define DIM     1024
#define HEADS   8
#define DHEAD   64
#define DINNER  512
#define QKV_N   1536

// Scratch (allocation-free rule: __device__ globals)
__device__ float g_scale[N_TOK];
__device__ float g_qkv[(size_t)N_TOK * QKV_N];
__device__ float g_ao[(size_t)N_TOK * DINNER];

// ---------------------------------------------------------------------------
// Packed fp32x2 helpers (Blackwell sm_103a). A double is used purely as an
// opaque 64-bit register pair carrying two fp32 lanes {lo, hi}.
// ---------------------------------------------------------------------------
__device__ __forceinline__ double f2pack(float lo, float hi) {
    double r;
    asm("mov.b64 %0, {%1, %2};" : "=d"(r) : "f"(lo), "f"(hi));
    return r;
}
__device__ __forceinline__ void f2unpack(double v, float& lo, float& hi) {
    asm("mov.b64 {%0, %1}, %2;" : "=f"(lo), "=f"(hi) : "d"(v));
}
__device__ __forceinline__ double ffma2(double a, double b, double c) {
    double r;
    asm("fma.rn.f32x2 %0, %1, %2, %3;" : "=d"(r) : "d"(a), "d"(b), "d"(c));
    return r;
}
__device__ __forceinline__ double fmul2(double a, double b) {
    double r;
    asm("mul.rn.f32x2 %0, %1, %2;" : "=d"(r) : "d"(a), "d"(b));
    return r;
}

// ---------------------------------------------------------------------------
// Kernel 1: per-row RMS scale = sqrt(DIM) / max(||x_row||, 1e-12)
// ---------------------------------------------------------------------------
__global__ void rms_scale_kernel(const float* __restrict__ x) {
    int row = blockIdx.x;
    const float* xr = x + (size_t)row * DIM;
    float s = 0.f;
    for (int i = threadIdx.x; i < DIM; i += 256) {
        float v = xr[i];
        s += v * v;
    }
    #pragma unroll
    for (int o = 16; o; o >>= 1) s += __shfl_xor_sync(0xffffffffu, s, o);
    __shared__ float ws[8];
    if ((threadIdx.x & 31) == 0) ws[threadIdx.x >> 5] = s;
    __syncthreads();
    if (threadIdx.x == 0) {
        float t = 0.f;
        #pragma unroll
        for (int i = 0; i < 8; i++) t += ws[i];
        float norm = sqrtf(t);
        g_scale[row] = 32.0f / fmaxf(norm, 1e-12f);  // sqrt(1024) = 32
    }
}

// ---------------------------------------------------------------------------
// Packed-fp32 GEMM: C[M,N] = A[M,K] @ B[K,N].  BM=BN=128, BK=8, 256 threads,
// 8x8 micro-tile per thread computed as 8x4 f32x2 accumulators.
// A tile is stored transposed AND duplicated ({a,a} pairs) so the packed
// A-operand is one LDS.64 broadcast. B pairs come straight out of float4s.
// ---------------------------------------------------------------------------
template <bool FUSE_RMS>
__global__ __launch_bounds__(256)
void gemm128_kernel(const float* __restrict__ A, const float* __restrict__ B,
                    float* __restrict__ C, int M, int N, int K,
                    const float* __restrict__ rowscale,
                    const float* __restrict__ gamma) {
    __shared__ float Ad[8][258];   // [k][2*m] duplicated pairs
    __shared__ float Bs[8][132];   // [k][n]
    int tid = threadIdx.x;
    int tx = tid & 15, ty = tid >> 4;
    int m0 = blockIdx.y * 128, n0 = blockIdx.x * 128;

    int am = tid >> 1;            // 0..127 A-loader row
    int ak = (tid & 1) * 4;       // 0 or 4
    int bk = tid >> 5;            // 0..7  B-loader k
    int bn = (tid & 31) * 4;      // 0..124

    float rs = FUSE_RMS ? rowscale[m0 + am] : 0.f;

    double acc[8][4];
    #pragma unroll
    for (int i = 0; i < 8; i++)
        #pragma unroll
        for (int j = 0; j < 4; j++) acc[i][j] = 0.0;

    const float* Ap = A + (size_t)(m0 + am) * K + ak;
    const float* Bp = B + (size_t)bk * N + n0 + bn;

    for (int k0 = 0; k0 < K; k0 += 8) {
        float4 a4 = *(const float4*)(Ap + k0);
        if (FUSE_RMS) {
            a4.x *= rs * gamma[k0 + ak + 0];
            a4.y *= rs * gamma[k0 + ak + 1];
            a4.z *= rs * gamma[k0 + ak + 2];
            a4.w *= rs * gamma[k0 + ak + 3];
        }
        float4 b4 = *(const float4*)(Bp + (size_t)k0 * N);
        *(float2*)&Ad[ak + 0][2 * am] = make_float2(a4.x, a4.x);
        *(float2*)&Ad[ak + 1][2 * am] = make_float2(a4.y, a4.y);
        *(float2*)&Ad[ak + 2][2 * am] = make_float2(a4.z, a4.z);
        *(float2*)&Ad[ak + 3][2 * am] = make_float2(a4.w, a4.w);
        *(float4*)&Bs[bk][bn] = b4;
        __syncthreads();
        #pragma unroll
        for (int kk = 0; kk < 8; kk++) {
            double2 bA = *(const double2*)&Bs[kk][8 * tx];
            double2 bB = *(const double2*)&Bs[kk][8 * tx + 4];
            #pragma unroll
            for (int i = 0; i < 8; i++) {
                double a = *(const double*)&Ad[kk][2 * (8 * ty + i)];
                acc[i][0] = ffma2(a, bA.x, acc[i][0]);
                acc[i][1] = ffma2(a, bA.y, acc[i][1]);
                acc[i][2] = ffma2(a, bB.x, acc[i][2]);
                acc[i][3] = ffma2(a, bB.y, acc[i][3]);
            }
        }
        __syncthreads();
    }
    #pragma unroll
    for (int i = 0; i < 8; i++) {
        float f[8];
        #pragma unroll
        for (int j = 0; j < 4; j++) f2unpack(acc[i][j], f[2 * j], f[2 * j + 1]);
        float* cp = C + (size_t)(m0 + 8 * ty + i) * N + n0 + 8 * tx;
        *(float4*)cp       = make_float4(f[0], f[1], f[2], f[3]);
        *(float4*)(cp + 4) = make_float4(f[4], f[5], f[6], f[7]);
    }
}

// ---------------------------------------------------------------------------
// Kernel 3: causal flash attention, packed-fp32 GEMM structure.
// Grid (64 qtiles, 8 heads), 128 threads: thread (ty 0..15, tx 0..7) owns a
// 4-row x 8-col tile of the 64x64 block. Q (d-major, duplicated pairs) and
// P (j-major, duplicated pairs) live in smem so both GEMMs are LDS.64
// broadcast (A) x double2 (B) -> 16 FFMA2 outer products.
// q is pre-scaled by sqrt(d)=8 as in the reference.
// ---------------------------------------------------------------------------
#define ATT_SMEM ((64 * 130 + 64 * 68 + 64 * 68 + 64 * 130) * 4)

__global__ __launch_bounds__(128)
void attn_kernel(const float* __restrict__ qkv, float* __restrict__ ao) {
    extern __shared__ float sm[];
    float* Qd = sm;                    // [64][130]  [d][2*r] dup
    float* Ks = Qd + 64 * 130;         // [64][68]   [d][col]
    float* Vs = Ks + 64 * 68;          // [64][68]   [j][d]
    float* Pd = Vs + 64 * 68;          // [64][130]  [j][2*r] dup

    int qt = 63 - blockIdx.x;          // heavy tiles first
    int h  = blockIdx.y;
    int tid = threadIdx.x;
    int tx = tid & 7;
    int ty = tid >> 3;
    int r0 = 4 * ty;                   // rows r0..r0+3
    int c0 = 8 * tx;                   // cols c0..c0+7

    // Load Q tile: transpose to [d][row], duplicate pairs, scale by 8.
    for (int e = tid; e < 1024; e += 128) {
        int rr = e >> 4, d4 = (e & 15) * 4;
        float4 v = *(const float4*)(qkv + (size_t)(qt * 64 + rr) * QKV_N +
                                    h * DHEAD + d4);
        *(float2*)&Qd[(d4 + 0) * 130 + 2 * rr] = make_float2(v.x * 8.f, v.x * 8.f);
        *(float2*)&Qd[(d4 + 1) * 130 + 2 * rr] = make_float2(v.y * 8.f, v.y * 8.f);
        *(float2*)&Qd[(d4 + 2) * 130 + 2 * rr] = make_float2(v.z * 8.f, v.z * 8.f);
        *(float2*)&Qd[(d4 + 3) * 130 + 2 * rr] = make_float2(v.w * 8.f, v.w * 8.f);
    }

    double o2[4][4];
    #pragma unroll
    for (int i = 0; i < 4; i++)
        #pragma unroll
        for (int j = 0; j < 4; j++) o2[i][j] = 0.0;
    float m[4] = {-1e30f, -1e30f, -1e30f, -1e30f};
    float l[4] = {0.f, 0.f, 0.f, 0.f};

    for (int kt = 0; kt <= qt; kt++) {
        __syncthreads();   // protect previous tile's Ks/Vs/Pd
        for (int e = tid; e < 1024; e += 128) {
            int rr = e >> 4, d4 = (e & 15) * 4;
            const float* bp = qkv + (size_t)(kt * 64 + rr) * QKV_N +
                              h * DHEAD + d4;
            float4 kv = *(const float4*)(bp + DINNER);
            Ks[(d4 + 0) * 68 + rr] = kv.x;
            Ks[(d4 + 1) * 68 + rr] = kv.y;
            Ks[(d4 + 2) * 68 + rr] = kv.z;
            Ks[(d4 + 3) * 68 + rr] = kv.w;
            *(float4*)&Vs[rr * 68 + d4] = *(const float4*)(bp + 2 * DINNER);
        }
        __syncthreads();

        // ---- S = Q K^T (64 x 64 x 64) ----
        double s2[4][4];
        #pragma unroll
        for (int i = 0; i < 4; i++)
            #pragma unroll
            for (int j = 0; j < 4; j++) s2[i][j] = 0.0;
        #pragma unroll 16
        for (int d = 0; d < 64; d++) {
            double2 bA = *(const double2*)&Ks[d * 68 + c0];
            double2 bB = *(const double2*)&Ks[d * 68 + c0 + 4];
            #pragma unroll
            for (int i = 0; i < 4; i++) {
                double a = *(const double*)&Qd[d * 130 + 2 * (r0 + i)];
                s2[i][0] = ffma2(a, bA.x, s2[i][0]);
                s2[i][1] = ffma2(a, bA.y, s2[i][1]);
                s2[i][2] = ffma2(a, bB.x, s2[i][2]);
                s2[i][3] = ffma2(a, bB.y, s2[i][3]);
            }
        }

        float sv[4][8];
        #pragma unroll
        for (int i = 0; i < 4; i++)
            #pragma unroll
            for (int j = 0; j < 4; j++)
                f2unpack(s2[i][j], sv[i][2 * j], sv[i][2 * j + 1]);

        if (kt == qt) {   // causal mask only on the diagonal tile
            #pragma unroll
            for (int i = 0; i < 4; i++)
                #pragma unroll
                for (int j = 0; j < 8; j++)
                    if (c0 + j > r0 + i) sv[i][j] = -1e30f;
        }

        // ---- online softmax (row groups = 8 lanes) ----
        #pragma unroll
        for (int i = 0; i < 4; i++) {
            float mx = sv[i][0];
            #pragma unroll
            for (int j = 1; j < 8; j++) mx = fmaxf(mx, sv[i][j]);
            mx = fmaxf(mx, __shfl_xor_sync(0xffffffffu, mx, 1, 8));
            mx = fmaxf(mx, __shfl_xor_sync(0xffffffffu, mx, 2, 8));
            mx = fmaxf(mx, __shfl_xor_sync(0xffffffffu, mx, 4, 8));
            float mnew = fmaxf(m[i], mx);
            float corr = __expf(m[i] - mnew);
            m[i] = mnew;
            float sum = 0.f;
            #pragma unroll
            for (int j = 0; j < 8; j++) {
                float p = __expf(sv[i][j] - mnew);
                sv[i][j] = p;
                sum += p;
            }
            sum += __shfl_xor_sync(0xffffffffu, sum, 1, 8);
            sum += __shfl_xor_sync(0xffffffffu, sum, 2, 8);
            sum += __shfl_xor_sync(0xffffffffu, sum, 4, 8);
            l[i] = l[i] * corr + sum;
            double cd = f2pack(corr, corr);
            #pragma unroll
            for (int j = 0; j < 4; j++) o2[i][j] = fmul2(o2[i][j], cd);
            #pragma unroll
            for (int j = 0; j < 8; j++)
                *(float2*)&Pd[(c0 + j) * 130 + 2 * (r0 + i)] =
                    make_float2(sv[i][j], sv[i][j]);
        }
        __syncthreads();   // Pd complete before PV reads

        // ---- O += P V (64 x 64 x 64) ----
        #pragma unroll 16
        for (int jj = 0; jj < 64; jj++) {
            double2 vA = *(const double2*)&Vs[jj * 68 + c0];
            double2 vB = *(const double2*)&Vs[jj * 68 + c0 + 4];
            #pragma unroll
            for (int i = 0; i < 4; i++) {
                double a = *(const double*)&Pd[jj * 130 + 2 * (r0 + i)];
                o2[i][0] = ffma2(a, vA.x, o2[i][0]);
                o2[i][1] = ffma2(a, vA.y, o2[i][1]);
                o2[i][2] = ffma2(a, vB.x, o2[i][2]);
                o2[i][3] = ffma2(a, vB.y, o2[i][3]);
            }
        }
    }

    #pragma unroll
    for (int i = 0; i < 4; i++) {
        float inv = 1.f / l[i];
        float f[8];
        #pragma unroll
        for (int j = 0; j < 4; j++) f2unpack(o2[i][j], f[2 * j], f[2 * j + 1]);
        #pragma unroll
        for (int j = 0; j < 8; j++) f[j] *= inv;
        float* op = ao + (size_t)(qt * 64 + r0 + i) * DINNER + h * DHEAD + c0;
        *(float4*)op       = make_float4(f[0], f[1], f[2], f[3]);
        *(float4*)(op + 4) = make_float4(f[4], f[5], f[6], f[7]);
    }
}

// ---------------------------------------------------------------------------
extern "C" void kernel_launch(void* const* d_in, const int* in_sizes, int n_in,
                              void* d_out, int out_size) {
    const float* x     = (const float*)d_in[0];
    const float* gamma = (const float*)d_in[1];
    const float* w_qkv = (const float*)d_in[2];
    const float* w_out = (const float*)d_in[3];
    float* out = (float*)d_out;

    float *scale_p, *qkv_p, *ao_p;
    cudaGetSymbolAddress((void**)&scale_p, g_scale);
    cudaGetSymbolAddress((void**)&qkv_p, g_qkv);
    cudaGetSymbolAddress((void**)&ao_p, g_ao);

    cudaFuncSetAttribute(attn_kernel,
                         cudaFuncAttributeMaxDynamicSharedMemorySize, ATT_SMEM);

    rms_scale_kernel<<<N_TOK, 256>>>(x);

    gemm128_kernel<true><<<dim3(QKV_N / 128, N_TOK / 128), 256>>>(
        x, w_qkv, qkv_p, N_TOK, QKV_N, DIM, scale_p, gamma);

    attn_kernel<<<dim3(64, 8), 128, ATT_SMEM>>>(qkv_p, ao_p);

    gemm128_kernel<false><<<dim3(DIM / 128, N_TOK / 128), 256>>>(
        ao_p, w_out, out, N_TOK, DIM, DINNER, nullptr, nullptr);
}

// round 5
// speedup vs baseline: 3.9461x; 3.1373x over previous
#include <cuda_runtime.h>
#include <cuda_bf16.h>
#include <math.h>
#include <stdint.h>

#define N_TOK   4096
#define DIM     1024
#define HEADS   8
#define DHEAD   64
#define DINNER  512
#define QKV_N   1536

// Scratch (allocation-free rule: __device__ globals)
__device__ float g_scale[N_TOK];
__device__ __nv_bfloat16 g_xh[(size_t)N_TOK * DIM],    g_xl[(size_t)N_TOK * DIM];
__device__ __nv_bfloat16 g_wqh[(size_t)DIM * QKV_N],   g_wql[(size_t)DIM * QKV_N];
__device__ __nv_bfloat16 g_woh[(size_t)DINNER * DIM],  g_wol[(size_t)DINNER * DIM];
__device__ __nv_bfloat16 g_qkvh[(size_t)N_TOK * QKV_N], g_qkvl[(size_t)N_TOK * QKV_N];
__device__ __nv_bfloat16 g_aoh[(size_t)N_TOK * DINNER], g_aol[(size_t)N_TOK * DINNER];

// ---------------------------------------------------------------------------
// mma.sync m16n8k16 bf16 (row.col) with fp32 accumulate
// ---------------------------------------------------------------------------
__device__ __forceinline__ void mma16816(float* c,
    uint32_t a0, uint32_t a1, uint32_t a2, uint32_t a3,
    uint32_t b0, uint32_t b1) {
    asm volatile(
        "mma.sync.aligned.m16n8k16.row.col.f32.bf16.bf16.f32 "
        "{%0,%1,%2,%3}, {%4,%5,%6,%7}, {%8,%9}, {%0,%1,%2,%3};"
        : "+f"(c[0]), "+f"(c[1]), "+f"(c[2]), "+f"(c[3])
        : "r"(a0), "r"(a1), "r"(a2), "r"(a3), "r"(b0), "r"(b1));
}

__device__ __forceinline__ void ldsm2t(uint32_t& r0, uint32_t& r1, const void* p) {
    uint32_t a = (uint32_t)__cvta_generic_to_shared(p);
    asm volatile("ldmatrix.sync.aligned.m8n8.x2.trans.shared.b16 {%0,%1}, [%2];"
                 : "=r"(r0), "=r"(r1) : "r"(a));
}

// split a pair of fp32 into packed bf16 hi and lo (lo = residual)
__device__ __forceinline__ void split2(float v0, float v1,
                                       uint32_t& hi, uint32_t& lo) {
    __nv_bfloat16 h0 = __float2bfloat16_rn(v0);
    __nv_bfloat16 h1 = __float2bfloat16_rn(v1);
    __nv_bfloat16 l0 = __float2bfloat16_rn(v0 - __bfloat162float(h0));
    __nv_bfloat16 l1 = __float2bfloat16_rn(v1 - __bfloat162float(h1));
    __nv_bfloat162 hp; hp.x = h0; hp.y = h1;
    __nv_bfloat162 lp; lp.x = l0; lp.y = l1;
    hi = *(uint32_t*)&hp;
    lo = *(uint32_t*)&lp;
}

// ---------------------------------------------------------------------------
// Kernel 1: per-row RMS scale = sqrt(DIM) / max(||x_row||, 1e-12)
// ---------------------------------------------------------------------------
__global__ void rms_scale_kernel(const float* __restrict__ x) {
    int row = blockIdx.x;
    const float* xr = x + (size_t)row * DIM;
    float s = 0.f;
    for (int i = threadIdx.x; i < DIM; i += 256) {
        float v = xr[i];
        s += v * v;
    }
    #pragma unroll
    for (int o = 16; o; o >>= 1) s += __shfl_xor_sync(0xffffffffu, s, o);
    __shared__ float ws[8];
    if ((threadIdx.x & 31) == 0) ws[threadIdx.x >> 5] = s;
    __syncthreads();
    if (threadIdx.x == 0) {
        float t = 0.f;
        #pragma unroll
        for (int i = 0; i < 8; i++) t += ws[i];
        g_scale[row] = 32.0f / fmaxf(sqrtf(t), 1e-12f);
    }
}

// ---------------------------------------------------------------------------
// Split kernels: fp32 -> bf16 hi/lo pairs
// ---------------------------------------------------------------------------
__global__ void split_x_kernel(const float4* __restrict__ x,
                               const float* __restrict__ gamma) {
    int i = blockIdx.x * 256 + threadIdx.x;   // 4-elem chunk id, 1048576 total
    float4 v = x[i];
    int row = i >> 8;                          // DIM/4 = 256 chunks per row
    int col = (i & 255) * 4;
    float s = g_scale[row];
    float4 gm = *(const float4*)(gamma + col);
    float a0 = v.x * s * gm.x, a1 = v.y * s * gm.y;
    float a2 = v.z * s * gm.z, a3 = v.w * s * gm.w;
    uint32_t h0, l0, h1, l1;
    split2(a0, a1, h0, l0);
    split2(a2, a3, h1, l1);
    *(uint2*)&g_xh[(size_t)4 * i] = make_uint2(h0, h1);
    *(uint2*)&g_xl[(size_t)4 * i] = make_uint2(l0, l1);
}

__global__ void split_w_kernel(const float4* __restrict__ w,
                               __nv_bfloat16* __restrict__ hi,
                               __nv_bfloat16* __restrict__ lo) {
    int i = blockIdx.x * 256 + threadIdx.x;
    float4 v = w[i];
    uint32_t h0, l0, h1, l1;
    split2(v.x, v.y, h0, l0);
    split2(v.z, v.w, h1, l1);
    *(uint2*)&hi[(size_t)4 * i] = make_uint2(h0, h1);
    *(uint2*)&lo[(size_t)4 * i] = make_uint2(l0, l1);
}

// ---------------------------------------------------------------------------
// bf16-split GEMM: C = (Ah+Al) @ (Bh+Bl), 3-product emulation.
// Block tile 128(M) x 64(N), BK=32, 256 threads = 8 warps (4m x 2n),
// warp tile 32x32 = 2 m16-tiles x 4 n8-tiles.
// If SPLIT_OUT, writes hi/lo bf16 split of C instead of fp32.
// ---------------------------------------------------------------------------
template <bool SPLIT_OUT>
__global__ __launch_bounds__(256)
void mma_gemm_kernel(const __nv_bfloat16* __restrict__ Ah,
                     const __nv_bfloat16* __restrict__ Al,
                     const __nv_bfloat16* __restrict__ Bh,
                     const __nv_bfloat16* __restrict__ Bl,
                     float* __restrict__ C,
                     __nv_bfloat16* __restrict__ Ch,
                     __nv_bfloat16* __restrict__ Cl,
                     int M, int N, int K) {
    __shared__ __align__(16) __nv_bfloat16 As[2][128][40];
    __shared__ __align__(16) __nv_bfloat16 Bs[2][32][72];
    int tid = threadIdx.x;
    int wid = tid >> 5, lane = tid & 31;
    int g = lane >> 2, t = lane & 3;
    int wm = wid & 3, wn = wid >> 2;
    int m0 = blockIdx.y * 128, n0 = blockIdx.x * 64;

    float c[2][4][4];
    #pragma unroll
    for (int mt = 0; mt < 2; mt++)
        #pragma unroll
        for (int nt = 0; nt < 4; nt++)
            #pragma unroll
            for (int e = 0; e < 4; e++) c[mt][nt][e] = 0.f;

    for (int k0 = 0; k0 < K; k0 += 32) {
        #pragma unroll
        for (int i = 0; i < 2; i++) {
            int p = tid + 256 * i;
            int ar = p >> 2, ak = (p & 3) * 8;
            *(uint4*)&As[0][ar][ak] = *(const uint4*)&Ah[(size_t)(m0 + ar) * K + k0 + ak];
            *(uint4*)&As[1][ar][ak] = *(const uint4*)&Al[(size_t)(m0 + ar) * K + k0 + ak];
        }
        {
            int br = tid >> 3, bn = (tid & 7) * 8;
            *(uint4*)&Bs[0][br][bn] = *(const uint4*)&Bh[(size_t)(k0 + br) * N + n0 + bn];
            *(uint4*)&Bs[1][br][bn] = *(const uint4*)&Bl[(size_t)(k0 + br) * N + n0 + bn];
        }
        __syncthreads();
        #pragma unroll
        for (int kk = 0; kk < 32; kk += 16) {
            uint32_t ah[2][4], al[2][4];
            #pragma unroll
            for (int mt = 0; mt < 2; mt++) {
                int r = wm * 32 + mt * 16;
                ah[mt][0] = *(const uint32_t*)&As[0][r + g][kk + 2 * t];
                ah[mt][1] = *(const uint32_t*)&As[0][r + 8 + g][kk + 2 * t];
                ah[mt][2] = *(const uint32_t*)&As[0][r + g][kk + 8 + 2 * t];
                ah[mt][3] = *(const uint32_t*)&As[0][r + 8 + g][kk + 8 + 2 * t];
                al[mt][0] = *(const uint32_t*)&As[1][r + g][kk + 2 * t];
                al[mt][1] = *(const uint32_t*)&As[1][r + 8 + g][kk + 2 * t];
                al[mt][2] = *(const uint32_t*)&As[1][r + g][kk + 8 + 2 * t];
                al[mt][3] = *(const uint32_t*)&As[1][r + 8 + g][kk + 8 + 2 * t];
            }
            #pragma unroll
            for (int nt = 0; nt < 4; nt++) {
                uint32_t bh0, bh1, bl0, bl1;
                ldsm2t(bh0, bh1, &Bs[0][kk + (lane & 15)][wn * 32 + nt * 8]);
                ldsm2t(bl0, bl1, &Bs[1][kk + (lane & 15)][wn * 32 + nt * 8]);
                #pragma unroll
                for (int mt = 0; mt < 2; mt++) {
                    mma16816(c[mt][nt], ah[mt][0], ah[mt][1], ah[mt][2], ah[mt][3], bh0, bh1);
                    mma16816(c[mt][nt], ah[mt][0], ah[mt][1], ah[mt][2], ah[mt][3], bl0, bl1);
                    mma16816(c[mt][nt], al[mt][0], al[mt][1], al[mt][2], al[mt][3], bh0, bh1);
                }
            }
        }
        __syncthreads();
    }
    #pragma unroll
    for (int mt = 0; mt < 2; mt++) {
        #pragma unroll
        for (int nt = 0; nt < 4; nt++) {
            int rowA = m0 + wm * 32 + mt * 16 + g;
            int col = n0 + wn * 32 + nt * 8 + 2 * t;
            if (SPLIT_OUT) {
                uint32_t hi, lo;
                split2(c[mt][nt][0], c[mt][nt][1], hi, lo);
                *(uint32_t*)&Ch[(size_t)rowA * N + col] = hi;
                *(uint32_t*)&Cl[(size_t)rowA * N + col] = lo;
                split2(c[mt][nt][2], c[mt][nt][3], hi, lo);
                *(uint32_t*)&Ch[(size_t)(rowA + 8) * N + col] = hi;
                *(uint32_t*)&Cl[(size_t)(rowA + 8) * N + col] = lo;
            } else {
                *(float2*)&C[(size_t)rowA * N + col] =
                    make_float2(c[mt][nt][0], c[mt][nt][1]);
                *(float2*)&C[(size_t)(rowA + 8) * N + col] =
                    make_float2(c[mt][nt][2], c[mt][nt][3]);
            }
        }
    }
}

// ---------------------------------------------------------------------------
// Flash attention on mma.sync bf16-split.
// Grid (64 qtiles, 8 heads), 128 threads = 4 warps; warp owns 16 Q rows.
// Q/K frags: direct LDS.32 (conflict-free 72-elem row pad);
// V frags: ldmatrix.x2.trans; P stays in registers (C-frag -> A-frag).
// Logits scaled by sqrt(d)=8 AFTER the mma (keeps split operands ~N(0,1)).
// ---------------------------------------------------------------------------
#define ASM_ELE (64 * 72)
#define ATT_SMEM (6 * ASM_ELE * 2)

__global__ __launch_bounds__(128)
void mma_attn_kernel(const __nv_bfloat16* __restrict__ qh,
                     const __nv_bfloat16* __restrict__ ql,
                     __nv_bfloat16* __restrict__ aoh,
                     __nv_bfloat16* __restrict__ aol) {
    extern __shared__ __align__(16) __nv_bfloat16 smb[];
    __nv_bfloat16* Qh = smb;
    __nv_bfloat16* Ql = smb + ASM_ELE;
    __nv_bfloat16* Kh = smb + 2 * ASM_ELE;
    __nv_bfloat16* Kl = smb + 3 * ASM_ELE;
    __nv_bfloat16* Vh = smb + 4 * ASM_ELE;
    __nv_bfloat16* Vl = smb + 5 * ASM_ELE;

    int qt = 63 - blockIdx.x;          // heavy tiles first
    int h = blockIdx.y;
    int tid = threadIdx.x;
    int wid = tid >> 5, lane = tid & 31;
    int g = lane >> 2, t = lane & 3;
    int r0 = wid * 16;

    for (int p = tid; p < 512; p += 128) {
        int rr = p >> 3, c8 = (p & 7) * 8;
        size_t src = (size_t)(qt * 64 + rr) * QKV_N + h * DHEAD + c8;
        *(uint4*)&Qh[rr * 72 + c8] = *(const uint4*)&qh[src];
        *(uint4*)&Ql[rr * 72 + c8] = *(const uint4*)&ql[src];
    }

    float o[8][4];
    #pragma unroll
    for (int nt = 0; nt < 8; nt++)
        #pragma unroll
        for (int e = 0; e < 4; e++) o[nt][e] = 0.f;
    float m[2] = {-1e30f, -1e30f}, l[2] = {0.f, 0.f};

    for (int kt = 0; kt <= qt; kt++) {
        __syncthreads();
        for (int p = tid; p < 512; p += 128) {
            int rr = p >> 3, c8 = (p & 7) * 8;
            size_t base = (size_t)(kt * 64 + rr) * QKV_N + h * DHEAD + c8;
            *(uint4*)&Kh[rr * 72 + c8] = *(const uint4*)&qh[base + DINNER];
            *(uint4*)&Kl[rr * 72 + c8] = *(const uint4*)&ql[base + DINNER];
            *(uint4*)&Vh[rr * 72 + c8] = *(const uint4*)&qh[base + 2 * DINNER];
            *(uint4*)&Vl[rr * 72 + c8] = *(const uint4*)&ql[base + 2 * DINNER];
        }
        __syncthreads();

        float sc[8][4];
        #pragma unroll
        for (int nt = 0; nt < 8; nt++)
            #pragma unroll
            for (int e = 0; e < 4; e++) sc[nt][e] = 0.f;

        #pragma unroll
        for (int d16 = 0; d16 < 4; d16++) {
            uint32_t ah0 = *(const uint32_t*)&Qh[(r0 + g) * 72 + d16 * 16 + 2 * t];
            uint32_t ah1 = *(const uint32_t*)&Qh[(r0 + 8 + g) * 72 + d16 * 16 + 2 * t];
            uint32_t ah2 = *(const uint32_t*)&Qh[(r0 + g) * 72 + d16 * 16 + 8 + 2 * t];
            uint32_t ah3 = *(const uint32_t*)&Qh[(r0 + 8 + g) * 72 + d16 * 16 + 8 + 2 * t];
            uint32_t al0 = *(const uint32_t*)&Ql[(r0 + g) * 72 + d16 * 16 + 2 * t];
            uint32_t al1 = *(const uint32_t*)&Ql[(r0 + 8 + g) * 72 + d16 * 16 + 2 * t];
            uint32_t al2 = *(const uint32_t*)&Ql[(r0 + g) * 72 + d16 * 16 + 8 + 2 * t];
            uint32_t al3 = *(const uint32_t*)&Ql[(r0 + 8 + g) * 72 + d16 * 16 + 8 + 2 * t];
            #pragma unroll
            for (int nt = 0; nt < 8; nt++) {
                uint32_t bh0 = *(const uint32_t*)&Kh[(nt * 8 + g) * 72 + d16 * 16 + 2 * t];
                uint32_t bh1 = *(const uint32_t*)&Kh[(nt * 8 + g) * 72 + d16 * 16 + 8 + 2 * t];
                uint32_t bl0 = *(const uint32_t*)&Kl[(nt * 8 + g) * 72 + d16 * 16 + 2 * t];
                uint32_t bl1 = *(const uint32_t*)&Kl[(nt * 8 + g) * 72 + d16 * 16 + 8 + 2 * t];
                mma16816(sc[nt], ah0, ah1, ah2, ah3, bh0, bh1);
                mma16816(sc[nt], ah0, ah1, ah2, ah3, bl0, bl1);
                mma16816(sc[nt], al0, al1, al2, al3, bh0, bh1);
            }
        }

        #pragma unroll
        for (int nt = 0; nt < 8; nt++)
            #pragma unroll
            for (int e = 0; e < 4; e++) sc[nt][e] *= 8.f;

        if (kt == qt) {
            #pragma unroll
            for (int nt = 0; nt < 8; nt++) {
                int colb = nt * 8 + 2 * t;
                int rA = r0 + g, rB = r0 + 8 + g;
                if (colb > rA)     sc[nt][0] = -1e30f;
                if (colb + 1 > rA) sc[nt][1] = -1e30f;
                if (colb > rB)     sc[nt][2] = -1e30f;
                if (colb + 1 > rB) sc[nt][3] = -1e30f;
            }
        }

        #pragma unroll
        for (int hf = 0; hf < 2; hf++) {
            float mx = -1e30f;
            #pragma unroll
            for (int nt = 0; nt < 8; nt++) {
                mx = fmaxf(mx, sc[nt][2 * hf]);
                mx = fmaxf(mx, sc[nt][2 * hf + 1]);
            }
            mx = fmaxf(mx, __shfl_xor_sync(0xffffffffu, mx, 1));
            mx = fmaxf(mx, __shfl_xor_sync(0xffffffffu, mx, 2));
            float mnew = fmaxf(m[hf], mx);
            float corr = __expf(m[hf] - mnew);
            m[hf] = mnew;
            float sum = 0.f;
            #pragma unroll
            for (int nt = 0; nt < 8; nt++) {
                float p0 = __expf(sc[nt][2 * hf] - mnew);
                float p1 = __expf(sc[nt][2 * hf + 1] - mnew);
                sc[nt][2 * hf] = p0;
                sc[nt][2 * hf + 1] = p1;
                sum += p0 + p1;
            }
            sum += __shfl_xor_sync(0xffffffffu, sum, 1);
            sum += __shfl_xor_sync(0xffffffffu, sum, 2);
            l[hf] = l[hf] * corr + sum;
            #pragma unroll
            for (int nt = 0; nt < 8; nt++) {
                o[nt][2 * hf] *= corr;
                o[nt][2 * hf + 1] *= corr;
            }
        }

        // P: C-frag -> A-frag register conversion with hi/lo split
        uint32_t ph[4][4], pl[4][4];
        #pragma unroll
        for (int kk = 0; kk < 4; kk++) {
            split2(sc[2 * kk][0], sc[2 * kk][1], ph[kk][0], pl[kk][0]);
            split2(sc[2 * kk][2], sc[2 * kk][3], ph[kk][1], pl[kk][1]);
            split2(sc[2 * kk + 1][0], sc[2 * kk + 1][1], ph[kk][2], pl[kk][2]);
            split2(sc[2 * kk + 1][2], sc[2 * kk + 1][3], ph[kk][3], pl[kk][3]);
        }

        #pragma unroll
        for (int nt = 0; nt < 8; nt++) {
            #pragma unroll
            for (int kk = 0; kk < 4; kk++) {
                uint32_t vh0, vh1, vl0, vl1;
                ldsm2t(vh0, vh1, &Vh[(kk * 16 + (lane & 15)) * 72 + nt * 8]);
                ldsm2t(vl0, vl1, &Vl[(kk * 16 + (lane & 15)) * 72 + nt * 8]);
                mma16816(o[nt], ph[kk][0], ph[kk][1], ph[kk][2], ph[kk][3], vh0, vh1);
                mma16816(o[nt], ph[kk][0], ph[kk][1], ph[kk][2], ph[kk][3], vl0, vl1);
                mma16816(o[nt], pl[kk][0], pl[kk][1], pl[kk][2], pl[kk][3], vh0, vh1);
            }
        }
    }

    float inv0 = 1.f / l[0], inv1 = 1.f / l[1];
    #pragma unroll
    for (int nt = 0; nt < 8; nt++) {
        int col = h * DHEAD + nt * 8 + 2 * t;
        size_t rA = (size_t)(qt * 64 + r0 + g) * DINNER + col;
        size_t rB = (size_t)(qt * 64 + r0 + 8 + g) * DINNER + col;
        uint32_t hi, lo;
        split2(o[nt][0] * inv0, o[nt][1] * inv0, hi, lo);
        *(uint32_t*)&aoh[rA] = hi;
        *(uint32_t*)&aol[rA] = lo;
        split2(o[nt][2] * inv1, o[nt][3] * inv1, hi, lo);
        *(uint32_t*)&aoh[rB] = hi;
        *(uint32_t*)&aol[rB] = lo;
    }
}

// ---------------------------------------------------------------------------
extern "C" void kernel_launch(void* const* d_in, const int* in_sizes, int n_in,
                              void* d_out, int out_size) {
    const float* x     = (const float*)d_in[0];
    const float* gamma = (const float*)d_in[1];
    const float* w_qkv = (const float*)d_in[2];
    const float* w_out = (const float*)d_in[3];
    float* out = (float*)d_out;

    __nv_bfloat16 *xh, *xl, *wqh, *wql, *woh, *wol, *qkvh, *qkvl, *aoh, *aol;
    cudaGetSymbolAddress((void**)&xh, g_xh);
    cudaGetSymbolAddress((void**)&xl, g_xl);
    cudaGetSymbolAddress((void**)&wqh, g_wqh);
    cudaGetSymbolAddress((void**)&wql, g_wql);
    cudaGetSymbolAddress((void**)&woh, g_woh);
    cudaGetSymbolAddress((void**)&wol, g_wol);
    cudaGetSymbolAddress((void**)&qkvh, g_qkvh);
    cudaGetSymbolAddress((void**)&qkvl, g_qkvl);
    cudaGetSymbolAddress((void**)&aoh, g_aoh);
    cudaGetSymbolAddress((void**)&aol, g_aol);

    cudaFuncSetAttribute(mma_attn_kernel,
                         cudaFuncAttributeMaxDynamicSharedMemorySize, ATT_SMEM);

    rms_scale_kernel<<<N_TOK, 256>>>(x);
    split_x_kernel<<<(N_TOK * DIM / 4) / 256, 256>>>((const float4*)x, gamma);
    split_w_kernel<<<(DIM * QKV_N / 4) / 256, 256>>>((const float4*)w_qkv, wqh, wql);
    split_w_kernel<<<(DINNER * DIM / 4) / 256, 256>>>((const float4*)w_out, woh, wol);

    mma_gemm_kernel<true><<<dim3(QKV_N / 64, N_TOK / 128), 256>>>(
        xh, xl, wqh, wql, nullptr, qkvh, qkvl, N_TOK, QKV_N, DIM);

    mma_attn_kernel<<<dim3(64, 8), 128, ATT_SMEM>>>(qkvh, qkvl, aoh, aol);

    mma_gemm_kernel<false><<<dim3(DIM / 64, N_TOK / 128), 256>>>(
        aoh, aol, woh, wol, out, nullptr, nullptr, N_TOK, DIM, DINNER);
}